// round 7
// baseline (speedup 1.0000x reference)
#include <cuda_runtime.h>
#include <cuda_fp16.h>
#include <cstdint>

#define BATCH  16384
#define D      512
#define OUTD   2048
#define NLAYER 4

#define BM 128
#define BN 128
#define NTILES 16
#define NROWB (BATCH / BM)                // 128
#define NITEMS (NLAYER * NROWB * 4)       // 2048
#define NSTAGE 6
#define STAGE_BYTES (BM * 64 + BN * 64)   // 16384
#define SMEM_MAIN (NSTAGE * STAGE_BYTES)  // 98304
#define SMEM_TOTAL (SMEM_MAIN + 1536)

__device__ float  g_wsum[NLAYER * D];
__device__ float  g_dot[3][3][BATCH];
__device__ float  g_sum[3][BATCH];
__device__ unsigned g_ready[3][NROWB];
__device__ __half g_h0[(size_t)BATCH * D];
__device__ __half g_h1[(size_t)BATCH * D];
__device__ __half g_wh[(size_t)NLAYER * D * D];

// ---------------- helpers ----------------
__device__ __forceinline__ uint32_t s2u(const void* p) {
    uint32_t a;
    asm("{ .reg .u64 t; cvta.to.shared.u64 t, %1; cvt.u32.u64 %0, t; }" : "=r"(a) : "l"(p));
    return a;
}
__device__ __forceinline__ uint64_t g2g(const void* p) {
    uint64_t a;
    asm("cvta.to.global.u64 %0, %1;" : "=l"(a) : "l"(p));
    return a;
}
__device__ __forceinline__ void cp16(uint32_t s, uint64_t g) {
    asm volatile("cp.async.cg.shared.global [%0], [%1], 16;" :: "r"(s), "l"(g) : "memory");
}
#define CP_COMMIT() asm volatile("cp.async.commit_group;" ::: "memory")
#define CP_WAIT4()  asm volatile("cp.async.wait_group 4;" ::: "memory")

__device__ __forceinline__ void ldsm4(uint32_t& r0, uint32_t& r1, uint32_t& r2, uint32_t& r3,
                                      uint32_t addr) {
    asm volatile("ldmatrix.sync.aligned.m8n8.x4.shared.b16 {%0,%1,%2,%3}, [%4];"
                 : "=r"(r0), "=r"(r1), "=r"(r2), "=r"(r3) : "r"(addr));
}
__device__ __forceinline__ void mma_f16(float* c, const uint32_t* a, const uint32_t* b) {
    asm volatile(
        "mma.sync.aligned.m16n8k16.row.col.f32.f16.f16.f32 "
        "{%0,%1,%2,%3}, {%4,%5,%6,%7}, {%8,%9}, {%0,%1,%2,%3};\n"
        : "+f"(c[0]), "+f"(c[1]), "+f"(c[2]), "+f"(c[3])
        : "r"(a[0]), "r"(a[1]), "r"(a[2]), "r"(a[3]), "r"(b[0]), "r"(b[1]));
}

// ---------------- zero accumulators ----------------
__global__ void zero_aux() {
    int i = blockIdx.x * blockDim.x + threadIdx.x;
    if (i < 9 * BATCH) ((float*)g_dot)[i] = 0.f;
    if (i < 3 * BATCH) ((float*)g_sum)[i] = 0.f;
    if (i < 3 * NROWB) ((unsigned*)g_ready)[i] = 0u;
}

// ---------------- prep: W -> fp16 + wsum ----------------
__global__ void prep_w(const float* __restrict__ W) {
    int warp = (blockIdx.x * blockDim.x + threadIdx.x) >> 5;
    int lane = threadIdx.x & 31;
    if (warp >= NLAYER * D) return;
    const float4* row = (const float4*)(W + (size_t)warp * D);
    __half* hrow = g_wh + (size_t)warp * D;
    float s = 0.f;
#pragma unroll
    for (int k = 0; k < 4; k++) {
        int i4 = lane + 32 * k;
        float4 v = row[i4];
        s += v.x + v.y + v.z + v.w;
        __half2 h01 = __floats2half2_rn(v.x, v.y);
        __half2 h23 = __floats2half2_rn(v.z, v.w);
        uint2 pk = make_uint2(*(uint32_t*)&h01, *(uint32_t*)&h23);
        *(uint2*)(hrow + i4 * 4) = pk;
    }
#pragma unroll
    for (int off = 16; off; off >>= 1) s += __shfl_xor_sync(0xffffffffu, s, off);
    if (lane == 0) g_wsum[warp] = s;
}

// ---------------- prep: x -> fp16 + row sums ----------------
__global__ void conv_x(const float* __restrict__ x) {
    int row  = (blockIdx.x * blockDim.x + threadIdx.x) >> 5;
    int lane = threadIdx.x & 31;
    const float4* rp = (const float4*)(x + (size_t)row * D);
    __half* hp = g_h0 + (size_t)row * D;
    float s = 0.f;
#pragma unroll
    for (int k = 0; k < 4; k++) {
        int i4 = lane + 32 * k;
        float4 v = rp[i4];
        s += v.x + v.y + v.z + v.w;
        __half2 h01 = __floats2half2_rn(v.x, v.y);
        __half2 h23 = __floats2half2_rn(v.z, v.w);
        uint2 pk = make_uint2(*(uint32_t*)&h01, *(uint32_t*)&h23);
        *(uint2*)(hp + i4 * 4) = pk;
    }
#pragma unroll
    for (int off = 16; off; off >>= 1) s += __shfl_xor_sync(0xffffffffu, s, off);
    if (lane == 0) g_sum[0][row] = s;
}

// ---------------- persistent fused network (128 thr, warp tile 64x64) --------
__global__ __launch_bounds__(128, 2)
void persist_net(const float* __restrict__ x,
                 const float* __restrict__ bias_all,
                 float* __restrict__ out_base)
{
    extern __shared__ __align__(128) char dsm[];
    uint32_t sb = s2u(dsm);
    float* wsum_s = (float*)(dsm + SMEM_MAIN);
    float* bias_s = (float*)(dsm + SMEM_MAIN + 512);
    float* c_s    = (float*)(dsm + SMEM_MAIN + 1024);

    int tid = threadIdx.x, warp = tid >> 5, lane = tid & 31;

    int wm = (warp >> 1) * 64;          // 0 / 64
    int wn = (warp & 1) * 64;           // 0 / 64
    int xa = ((lane & 15) >> 1) & 3;
    int rb = (lane & 7) + ((lane >> 4) << 3);
    int xb = (rb >> 1) & 3;
    int ahc = lane >> 4;
    int bhc = (lane >> 3) & 1;
    int u = tid & 3, r2 = tid >> 2;     // r2: 0..31
    uint32_t swz = (uint32_t)((u ^ ((r2 >> 1) & 3)) << 4);
    uint32_t sA0 = sb + r2 * 64 + swz;
    uint32_t sB0 = sb + BM * 64 + r2 * 64 + swz;
    uint32_t aRow = sb + (uint32_t)(wm + (lane & 15)) * 64;
    uint32_t bRow = sb + BM * 64 + (uint32_t)(wn + rb) * 64;
    int g = lane >> 2, t = lane & 3;

    for (int item = blockIdx.x; item < NITEMS; item += gridDim.x) {
        int layer = item >> 9;
        int ti    = item & 511;
        int rowb  = ti >> 2;
        int col   = ti & 3;
        int rowB  = rowb * BM, colB = col * BN;
        int asel  = layer & 1;
        int write_ah = (layer < NLAYER - 1);
        int ndots = (layer < 3) ? (layer + 1) : 0;
        int dosum = (layer <= 1);

        const __half* Ah = asel ? g_h1 : g_h0;
        __half*       Oh = asel ? g_h0 : g_h1;
        const __half* Wl = g_wh + (size_t)layer * D * D;
        float* out = out_base + layer * D;

        uint64_t gA = g2g(Ah + (size_t)(rowB + r2) * D + u * 8);
        uint64_t gB = g2g(Wl + (size_t)(colB + r2) * D + u * 8);

        // each thread: 4 rows of A (r2, r2+32, r2+64, r2+96), 4 rows of B
#define LOAD_A(kt, so)                                                    \
        {                                                                 \
            uint64_t go = (uint64_t)(kt) * 64;                            \
            cp16(sA0 + (so),         gA + go);                            \
            cp16(sA0 + (so) + 2048,  gA + go + 32768);                    \
            cp16(sA0 + (so) + 4096,  gA + go + 65536);                    \
            cp16(sA0 + (so) + 6144,  gA + go + 98304);                    \
        }
#define LOAD_B(kt, so)                                                    \
        {                                                                 \
            uint64_t go = (uint64_t)(kt) * 64;                            \
            cp16(sB0 + (so),         gB + go);                            \
            cp16(sB0 + (so) + 2048,  gB + go + 32768);                    \
            cp16(sB0 + (so) + 4096,  gB + go + 65536);                    \
            cp16(sB0 + (so) + 6144,  gB + go + 98304);                    \
        }

        // prefetch B (weights, producer-independent) while we may spin
        LOAD_B(0, 0);
        LOAD_B(1, STAGE_BYTES);
        LOAD_B(2, 2 * STAGE_BYTES);
        LOAD_B(3, 3 * STAGE_BYTES);
        LOAD_B(4, 4 * STAGE_BYTES);

        if (layer > 0) {
            if (tid == 0) {
                const unsigned* cp = &g_ready[layer - 1][rowb];
                unsigned v;
                while (true) {
                    asm volatile("ld.acquire.gpu.global.u32 %0, [%1];"
                                 : "=r"(v) : "l"(cp) : "memory");
                    if (v >= 4u) break;
                    __nanosleep(64);
                }
            }
            __syncthreads();
        }

        if (tid < 128) {
            wsum_s[tid] = g_wsum[layer * D + colB + tid];
            bias_s[tid] = bias_all[layer * D + colB + tid];
            float c = 0.f;
            if (layer > 0) {
                int row = rowB + tid;
#pragma unroll
                for (int j = 0; j < 3; j++)
                    if (j < layer)
                        c = c + g_dot[layer - 1][j][row] + c * g_sum[j][row];
            }
            c_s[tid] = c;
        }

        LOAD_A(0, 0);               CP_COMMIT();
        LOAD_A(1, STAGE_BYTES);     CP_COMMIT();
        LOAD_A(2, 2 * STAGE_BYTES); CP_COMMIT();
        LOAD_A(3, 3 * STAGE_BYTES); CP_COMMIT();
        LOAD_A(4, 4 * STAGE_BYTES); CP_COMMIT();

        float acc[4][8][4];
#pragma unroll
        for (int i = 0; i < 4; i++)
#pragma unroll
            for (int j = 0; j < 8; j++)
#pragma unroll
                for (int k = 0; k < 4; k++) acc[i][j][k] = 0.f;

        int stC = 0, stL = 5;
        for (int kt = 0; kt < NTILES; kt++) {
            CP_WAIT4();
            __syncthreads();
            if (kt + 5 < NTILES) {
                uint32_t soL = (uint32_t)stL * STAGE_BYTES;
                LOAD_A(kt + 5, soL);
                LOAD_B(kt + 5, soL);
                if (++stL == NSTAGE) stL = 0;
            }
            CP_COMMIT();

            uint32_t so = (uint32_t)stC * STAGE_BYTES;
            if (++stC == NSTAGE) stC = 0;
#pragma unroll
            for (int s16 = 0; s16 < 2; s16++) {
                uint32_t afr[4][4];
                uint32_t bfr[4][4];
                uint32_t ca = (uint32_t)(((2 * s16 + ahc) ^ xa) << 4);
                uint32_t cb = (uint32_t)(((2 * s16 + bhc) ^ xb) << 4);
#pragma unroll
                for (int mt = 0; mt < 4; mt++)
                    ldsm4(afr[mt][0], afr[mt][1], afr[mt][2], afr[mt][3],
                          aRow + so + (uint32_t)mt * 1024 + ca);
#pragma unroll
                for (int nb = 0; nb < 4; nb++)
                    ldsm4(bfr[nb][0], bfr[nb][1], bfr[nb][2], bfr[nb][3],
                          bRow + so + (uint32_t)nb * 1024 + cb);
#pragma unroll
                for (int mt = 0; mt < 4; mt++)
#pragma unroll
                    for (int nt = 0; nt < 8; nt++) {
                        uint32_t bpair[2] = { bfr[nt >> 1][(nt & 1) * 2],
                                              bfr[nt >> 1][(nt & 1) * 2 + 1] };
                        mma_f16(acc[mt][nt], afr[mt], bpair);
                    }
            }
        }

        // ---- epilogue ----
        const float* ajb[3];
        int ajs[3];
        ajb[0] = x;            ajs[0] = D;
        ajb[1] = out_base;     ajs[1] = OUTD;
        ajb[2] = out_base + D; ajs[2] = OUTD;

#pragma unroll
        for (int mt = 0; mt < 4; mt++) {
            int mloc = wm + mt * 16 + g;
            int m0 = rowB + mloc;
            float c0 = c_s[mloc];
            float c1 = c_s[mloc + 8];
            float* o0 = out + (size_t)m0 * OUTD + colB;
            float* o1 = o0 + (size_t)8 * OUTD;
            __half* h0 = Oh + (size_t)m0 * D + colB;
            __half* h1 = h0 + (size_t)8 * D;

            const float* p0[3];
#pragma unroll
            for (int j = 0; j < 3; j++)
                p0[j] = ajb[j] + (size_t)m0 * ajs[j] + colB;

            float dac0[4] = {0.f, 0.f, 0.f, 0.f};
            float dac1[4] = {0.f, 0.f, 0.f, 0.f};

#pragma unroll
            for (int nt = 0; nt < 8; nt++) {
                int cc = wn + nt * 8 + 2 * t;
                float w0 = wsum_s[cc], w1 = wsum_s[cc + 1];
                float bb0 = bias_s[cc], bb1 = bias_s[cc + 1];
                float v00 = acc[mt][nt][0] + c0 * w0 + bb0;
                float v01 = acc[mt][nt][1] + c0 * w1 + bb1;
                float v10 = acc[mt][nt][2] + c1 * w0 + bb0;
                float v11 = acc[mt][nt][3] + c1 * w1 + bb1;
                *(float2*)(o0 + cc) = make_float2(v00, v01);
                *(float2*)(o1 + cc) = make_float2(v10, v11);
                if (write_ah) {
                    *(__half2*)(h0 + cc) = __floats2half2_rn(v00, v01);
                    *(__half2*)(h1 + cc) = __floats2half2_rn(v10, v11);
                }
#pragma unroll
                for (int j = 0; j < 3; j++)
                    if (j < ndots) {
                        float2 u0 = *(const float2*)(p0[j] + cc);
                        float2 u1 = *(const float2*)(p0[j] + (size_t)8 * ajs[j] + cc);
                        dac0[j] += v00 * u0.x + v01 * u0.y;
                        dac1[j] += v10 * u1.x + v11 * u1.y;
                    }
                if (dosum) {
                    dac0[3] += v00 + v01;
                    dac1[3] += v10 + v11;
                }
            }

#pragma unroll
            for (int j = 0; j < 4; j++) {
                bool live = (j < ndots) || (j == 3 && dosum);
                if (!live) continue;
                float r0 = dac0[j], r1 = dac1[j];
                r0 += __shfl_xor_sync(0xffffffffu, r0, 1);
                r0 += __shfl_xor_sync(0xffffffffu, r0, 2);
                r1 += __shfl_xor_sync(0xffffffffu, r1, 1);
                r1 += __shfl_xor_sync(0xffffffffu, r1, 2);
                if (t == 0) {
                    if (j < 3) {
                        atomicAdd(&g_dot[layer][j][m0], r0);
                        atomicAdd(&g_dot[layer][j][m0 + 8], r1);
                    } else {
                        atomicAdd(&g_sum[layer + 1][m0], r0);
                        atomicAdd(&g_sum[layer + 1][m0 + 8], r1);
                    }
                }
            }
        }

        // ---- signal completion ----
        __threadfence();
        __syncthreads();
        if (tid == 0 && layer < 3) {
            asm volatile("red.release.gpu.global.add.u32 [%0], %1;"
                         :: "l"(&g_ready[layer][rowb]), "r"(1u) : "memory");
        }
    }
}

// ---------------------------------------------------------------------------
extern "C" void kernel_launch(void* const* d_in, const int* in_sizes, int n_in,
                              void* d_out, int out_size) {
    const float* x = (const float*)d_in[0];
    const float* W = (const float*)d_in[1];
    const float* b = (const float*)d_in[2];
    float* out = (float*)d_out;

    cudaFuncSetAttribute(persist_net, cudaFuncAttributeMaxDynamicSharedMemorySize, SMEM_TOTAL);

    int dev = 0, sms = 148;
    cudaGetDevice(&dev);
    cudaDeviceGetAttribute(&sms, cudaDevAttrMultiProcessorCount, dev);
    int grid = 2 * sms;                    // all CTAs resident -> safe ordering
    if (grid > NITEMS) grid = NITEMS;

    zero_aux<<<(9 * BATCH) / 256, 256>>>();
    prep_w<<<NLAYER * D / 8, 256>>>(W);
    conv_x<<<BATCH * 32 / 256, 256>>>(x);

    persist_net<<<grid, 128, SMEM_TOTAL>>>(x, b, out);
}

// round 8
// speedup vs baseline: 1.1384x; 1.1384x over previous
#include <cuda_runtime.h>
#include <cuda_fp16.h>
#include <cstdint>

#define BATCH  16384
#define D      512
#define OUTD   2048
#define NLAYER 4

#define BM 128
#define BN 128
#define NTILES 16
#define NROWB (BATCH / BM)                // 128
#define NITEMS (NLAYER * NROWB * 4)       // 2048
#define STAGE_BYTES (BM * 64 + BN * 64)   // 16384
#define SMEM_MAIN (4 * STAGE_BYTES)       // 65536
#define SMEM_TOTAL (SMEM_MAIN + 1536)

__device__ float  g_wsum[NLAYER * D];
__device__ float  g_dot[3][3][BATCH];
__device__ float  g_sum[3][BATCH];
__device__ unsigned g_ready[3][NROWB];
__device__ __half g_ha[4][(size_t)BATCH * D];   // fp16 activations a0..a3 (L2-resident)
__device__ __half g_wh[(size_t)NLAYER * D * D];

// ---------------- helpers ----------------
__device__ __forceinline__ uint32_t s2u(const void* p) {
    uint32_t a;
    asm("{ .reg .u64 t; cvta.to.shared.u64 t, %1; cvt.u32.u64 %0, t; }" : "=r"(a) : "l"(p));
    return a;
}
__device__ __forceinline__ uint64_t g2g(const void* p) {
    uint64_t a;
    asm("cvta.to.global.u64 %0, %1;" : "=l"(a) : "l"(p));
    return a;
}
__device__ __forceinline__ void cp16(uint32_t s, uint64_t g) {
    asm volatile("cp.async.cg.shared.global [%0], [%1], 16;" :: "r"(s), "l"(g) : "memory");
}
#define CP_COMMIT() asm volatile("cp.async.commit_group;" ::: "memory")
#define CP_WAIT2()  asm volatile("cp.async.wait_group 2;" ::: "memory")

__device__ __forceinline__ void ldsm4(uint32_t& r0, uint32_t& r1, uint32_t& r2, uint32_t& r3,
                                      uint32_t addr) {
    asm volatile("ldmatrix.sync.aligned.m8n8.x4.shared.b16 {%0,%1,%2,%3}, [%4];"
                 : "=r"(r0), "=r"(r1), "=r"(r2), "=r"(r3) : "r"(addr));
}
__device__ __forceinline__ void mma_f16(float* c, const uint32_t* a, const uint32_t* b) {
    asm volatile(
        "mma.sync.aligned.m16n8k16.row.col.f32.f16.f16.f32 "
        "{%0,%1,%2,%3}, {%4,%5,%6,%7}, {%8,%9}, {%0,%1,%2,%3};\n"
        : "+f"(c[0]), "+f"(c[1]), "+f"(c[2]), "+f"(c[3])
        : "r"(a[0]), "r"(a[1]), "r"(a[2]), "r"(a[3]), "r"(b[0]), "r"(b[1]));
}

// ---------------- zero accumulators ----------------
__global__ void zero_aux() {
    int i = blockIdx.x * blockDim.x + threadIdx.x;
    if (i < 9 * BATCH) ((float*)g_dot)[i] = 0.f;
    if (i < 3 * BATCH) ((float*)g_sum)[i] = 0.f;
    if (i < 3 * NROWB) ((unsigned*)g_ready)[i] = 0u;
}

// ---------------- prep: W -> fp16 + wsum ----------------
__global__ void prep_w(const float* __restrict__ W) {
    int warp = (blockIdx.x * blockDim.x + threadIdx.x) >> 5;
    int lane = threadIdx.x & 31;
    if (warp >= NLAYER * D) return;
    const float4* row = (const float4*)(W + (size_t)warp * D);
    __half* hrow = g_wh + (size_t)warp * D;
    float s = 0.f;
#pragma unroll
    for (int k = 0; k < 4; k++) {
        int i4 = lane + 32 * k;
        float4 v = row[i4];
        s += v.x + v.y + v.z + v.w;
        __half2 h01 = __floats2half2_rn(v.x, v.y);
        __half2 h23 = __floats2half2_rn(v.z, v.w);
        uint2 pk = make_uint2(*(uint32_t*)&h01, *(uint32_t*)&h23);
        *(uint2*)(hrow + i4 * 4) = pk;
    }
#pragma unroll
    for (int off = 16; off; off >>= 1) s += __shfl_xor_sync(0xffffffffu, s, off);
    if (lane == 0) g_wsum[warp] = s;
}

// ---------------- prep: x -> fp16 + row sums ----------------
__global__ void conv_x(const float* __restrict__ x) {
    int row  = (blockIdx.x * blockDim.x + threadIdx.x) >> 5;
    int lane = threadIdx.x & 31;
    const float4* rp = (const float4*)(x + (size_t)row * D);
    __half* hp = g_ha[0] + (size_t)row * D;
    float s = 0.f;
#pragma unroll
    for (int k = 0; k < 4; k++) {
        int i4 = lane + 32 * k;
        float4 v = rp[i4];
        s += v.x + v.y + v.z + v.w;
        __half2 h01 = __floats2half2_rn(v.x, v.y);
        __half2 h23 = __floats2half2_rn(v.z, v.w);
        uint2 pk = make_uint2(*(uint32_t*)&h01, *(uint32_t*)&h23);
        *(uint2*)(hp + i4 * 4) = pk;
    }
#pragma unroll
    for (int off = 16; off; off >>= 1) s += __shfl_xor_sync(0xffffffffu, s, off);
    if (lane == 0) g_sum[0][row] = s;
}

// ---------------- persistent fused network ----------------
__global__ __launch_bounds__(256, 2)
void persist_net(const float* __restrict__ x,
                 const float* __restrict__ bias_all,
                 float* __restrict__ out_base)
{
    extern __shared__ __align__(128) char dsm[];
    uint32_t sb = s2u(dsm);
    float* wsum_s = (float*)(dsm + SMEM_MAIN);
    float* bias_s = (float*)(dsm + SMEM_MAIN + 512);
    float* c_s    = (float*)(dsm + SMEM_MAIN + 1024);

    int tid = threadIdx.x, warp = tid >> 5, lane = tid & 31;

    int wm = (warp >> 2) * 64;
    int wn = (warp & 3) * 32;
    int xa = ((lane & 15) >> 1) & 3;
    int rb = (lane & 7) + ((lane >> 4) << 3);
    int xb = (rb >> 1) & 3;
    int ahc = lane >> 4;
    int bhc = (lane >> 3) & 1;
    int u = tid & 3, r = tid >> 2;
    uint32_t swz = (uint32_t)((u ^ ((r >> 1) & 3)) << 4);
    uint32_t sA0 = sb + r * 64 + swz;
    uint32_t sB0 = sb + BM * 64 + r * 64 + swz;
    uint32_t aRow = sb + (uint32_t)(wm + (lane & 15)) * 64;
    uint32_t bRow = sb + BM * 64 + (uint32_t)(wn + rb) * 64;
    int g = lane >> 2, t = lane & 3;

    for (int item = blockIdx.x; item < NITEMS; item += gridDim.x) {
        int layer = item >> 9;
        int ti    = item & 511;
        int rowb  = ti >> 2;
        int col   = ti & 3;
        int rowB  = rowb * BM, colB = col * BN;
        int write_ah = (layer < NLAYER - 1);
        int ndots = (layer < 3) ? (layer + 1) : 0;
        int dosum = (layer <= 1);

        const __half* Ah = g_ha[layer];
        __half*       Oh = g_ha[(layer < 3) ? (layer + 1) : 3];
        const __half* Wl = g_wh + (size_t)layer * D * D;
        float* out = out_base + layer * D;

        uint64_t gA = g2g(Ah + (size_t)(rowB + r) * D + u * 8);
        uint64_t gB = g2g(Wl + (size_t)(colB + r) * D + u * 8);

#define LOAD_A(kt, st)                                                    \
        {                                                                 \
            uint32_t so = (uint32_t)(st) * STAGE_BYTES;                   \
            uint64_t go = (uint64_t)(kt) * 64;                            \
            cp16(sA0 + so,        gA + go);                               \
            cp16(sA0 + so + 4096, gA + go + 65536);                       \
        }
#define LOAD_B(kt, st)                                                    \
        {                                                                 \
            uint32_t so = (uint32_t)(st) * STAGE_BYTES;                   \
            uint64_t go = (uint64_t)(kt) * 64;                            \
            cp16(sB0 + so,        gB + go);                               \
            cp16(sB0 + so + 4096, gB + go + 65536);                       \
        }

        // prefetch B (weights, producer-independent) while we may spin
        LOAD_B(0, 0); LOAD_B(1, 1); LOAD_B(2, 2);

        if (layer > 0) {
            if (tid == 0) {
                const unsigned* cp = &g_ready[layer - 1][rowb];
                unsigned v;
                while (true) {
                    asm volatile("ld.acquire.gpu.global.u32 %0, [%1];"
                                 : "=r"(v) : "l"(cp) : "memory");
                    if (v >= 4u) break;
                    __nanosleep(64);
                }
            }
            __syncthreads();
        }

        if (tid < 128) {
            wsum_s[tid] = g_wsum[layer * D + colB + tid];
            bias_s[tid] = bias_all[layer * D + colB + tid];
            float c = 0.f;
            if (layer > 0) {
                int row = rowB + tid;
#pragma unroll
                for (int j = 0; j < 3; j++)
                    if (j < layer)
                        c = c + g_dot[layer - 1][j][row] + c * g_sum[j][row];
            }
            c_s[tid] = c;
        }

        LOAD_A(0, 0); CP_COMMIT();
        LOAD_A(1, 1); CP_COMMIT();
        LOAD_A(2, 2); CP_COMMIT();

        float acc[4][4][4];
#pragma unroll
        for (int i = 0; i < 4; i++)
#pragma unroll
            for (int j = 0; j < 4; j++)
#pragma unroll
                for (int k = 0; k < 4; k++) acc[i][j][k] = 0.f;

        for (int kt = 0; kt < NTILES; kt++) {
            CP_WAIT2();
            __syncthreads();
            if (kt + 3 < NTILES) { LOAD_A(kt + 3, (kt + 3) & 3); LOAD_B(kt + 3, (kt + 3) & 3); }
            CP_COMMIT();

            uint32_t so = (uint32_t)(kt & 3) * STAGE_BYTES;
#pragma unroll
            for (int s16 = 0; s16 < 2; s16++) {
                uint32_t afr[4][4];
                uint32_t bfr[2][4];
                uint32_t ca = (uint32_t)(((2 * s16 + ahc) ^ xa) << 4);
                uint32_t cb = (uint32_t)(((2 * s16 + bhc) ^ xb) << 4);
#pragma unroll
                for (int mt = 0; mt < 4; mt++)
                    ldsm4(afr[mt][0], afr[mt][1], afr[mt][2], afr[mt][3],
                          aRow + so + (uint32_t)mt * 1024 + ca);
#pragma unroll
                for (int nb = 0; nb < 2; nb++)
                    ldsm4(bfr[nb][0], bfr[nb][1], bfr[nb][2], bfr[nb][3],
                          bRow + so + (uint32_t)nb * 1024 + cb);
#pragma unroll
                for (int mt = 0; mt < 4; mt++)
#pragma unroll
                    for (int nt = 0; nt < 4; nt++) {
                        uint32_t bpair[2] = { bfr[nt >> 1][(nt & 1) * 2],
                                              bfr[nt >> 1][(nt & 1) * 2 + 1] };
                        mma_f16(acc[mt][nt], afr[mt], bpair);
                    }
            }
        }

        // ---- epilogue: writes + fused dot/sum reductions (fp16 a_j reads) ----
#pragma unroll
        for (int mt = 0; mt < 4; mt++) {
            int mloc = wm + mt * 16 + g;
            int m0 = rowB + mloc;
            float c0 = c_s[mloc];
            float c1 = c_s[mloc + 8];
            float* o0 = out + (size_t)m0 * OUTD + colB;
            float* o1 = o0 + (size_t)8 * OUTD;
            __half* h0 = Oh + (size_t)m0 * D + colB;
            __half* h1 = h0 + (size_t)8 * D;

            const __half* ph[3];
#pragma unroll
            for (int j = 0; j < 3; j++)
                ph[j] = g_ha[j] + (size_t)m0 * D + colB;

            float dac0[4] = {0.f, 0.f, 0.f, 0.f};
            float dac1[4] = {0.f, 0.f, 0.f, 0.f};

#pragma unroll
            for (int nt = 0; nt < 4; nt++) {
                int cc = wn + nt * 8 + 2 * t;
                float w0 = wsum_s[cc], w1 = wsum_s[cc + 1];
                float bb0 = bias_s[cc], bb1 = bias_s[cc + 1];
                float v00 = acc[mt][nt][0] + c0 * w0 + bb0;
                float v01 = acc[mt][nt][1] + c0 * w1 + bb1;
                float v10 = acc[mt][nt][2] + c1 * w0 + bb0;
                float v11 = acc[mt][nt][3] + c1 * w1 + bb1;
                *(float2*)(o0 + cc) = make_float2(v00, v01);
                *(float2*)(o1 + cc) = make_float2(v10, v11);
                if (write_ah) {
                    *(__half2*)(h0 + cc) = __floats2half2_rn(v00, v01);
                    *(__half2*)(h1 + cc) = __floats2half2_rn(v10, v11);
                }
#pragma unroll
                for (int j = 0; j < 3; j++)
                    if (j < ndots) {
                        float2 u0 = __half22float2(*(const __half2*)(ph[j] + cc));
                        float2 u1 = __half22float2(*(const __half2*)(ph[j] + 8 * D + cc));
                        dac0[j] += v00 * u0.x + v01 * u0.y;
                        dac1[j] += v10 * u1.x + v11 * u1.y;
                    }
                if (dosum) {
                    dac0[3] += v00 + v01;
                    dac1[3] += v10 + v11;
                }
            }

#pragma unroll
            for (int j = 0; j < 4; j++) {
                bool live = (j < ndots) || (j == 3 && dosum);
                if (!live) continue;
                float r0 = dac0[j], r1 = dac1[j];
                r0 += __shfl_xor_sync(0xffffffffu, r0, 1);
                r0 += __shfl_xor_sync(0xffffffffu, r0, 2);
                r1 += __shfl_xor_sync(0xffffffffu, r1, 1);
                r1 += __shfl_xor_sync(0xffffffffu, r1, 2);
                if (t == 0) {
                    if (j < 3) {
                        atomicAdd(&g_dot[layer][j][m0], r0);
                        atomicAdd(&g_dot[layer][j][m0 + 8], r1);
                    } else {
                        atomicAdd(&g_sum[layer + 1][m0], r0);
                        atomicAdd(&g_sum[layer + 1][m0 + 8], r1);
                    }
                }
            }
        }

        // ---- signal completion ----
        __threadfence();
        __syncthreads();
        if (tid == 0 && layer < 3) {
            asm volatile("red.release.gpu.global.add.u32 [%0], %1;"
                         :: "l"(&g_ready[layer][rowb]), "r"(1u) : "memory");
        }
    }
}

// ---------------------------------------------------------------------------
extern "C" void kernel_launch(void* const* d_in, const int* in_sizes, int n_in,
                              void* d_out, int out_size) {
    const float* x = (const float*)d_in[0];
    const float* W = (const float*)d_in[1];
    const float* b = (const float*)d_in[2];
    float* out = (float*)d_out;

    cudaFuncSetAttribute(persist_net, cudaFuncAttributeMaxDynamicSharedMemorySize, SMEM_TOTAL);

    int dev = 0, sms = 148;
    cudaGetDevice(&dev);
    cudaDeviceGetAttribute(&sms, cudaDevAttrMultiProcessorCount, dev);
    int grid = 2 * sms;
    if (grid > NITEMS) grid = NITEMS;

    zero_aux<<<(9 * BATCH) / 256, 256>>>();
    prep_w<<<NLAYER * D / 8, 256>>>(W);
    conv_x<<<BATCH * 32 / 256, 256>>>(x);

    persist_net<<<grid, 256, SMEM_TOTAL>>>(x, b, out);
}